// round 14
// baseline (speedup 1.0000x reference)
#include <cuda_runtime.h>
#include <cuda_fp16.h>

#define B_   8
#define TE_  512
#define TD_  128
#define H_   256
#define ESPLIT 4

// Scratch (allocation-free rule: device globals)
__device__ float g_ep[B_ * TE_ * H_];      // enc @ W_a   [B,TE,H]
__device__ float g_dp[B_ * TD_ * H_];      // dec @ U_a   [B,TD,H]
__device__ float g_score[B_ * TD_ * TE_];  // raw scores -> weights (in place)
__device__ float g_part[ESPLIT][B_ * TD_ * H_];  // ctx partial sums (4 MB)

__device__ __forceinline__ unsigned tanh2_fast(unsigned x2) {
    unsigned y2;
    asm("tanh.approx.f16x2 %0, %1;" : "=r"(y2) : "r"(x2));
    return y2;
}
__device__ __forceinline__ void ffma2(unsigned long long& d,
                                      unsigned long long a,
                                      unsigned long long b) {
    asm("fma.rn.f32x2 %0, %1, %2, %0;" : "+l"(d) : "l"(a), "l"(b));
}
__device__ __forceinline__ unsigned long long rep2(float x) {
    unsigned long long p;
    asm("mov.b64 %0, {%1, %1};" : "=l"(p) : "r"(__float_as_uint(x)));
    return p;
}
__device__ __forceinline__ unsigned long long pk2(float lo, float hi) {
    unsigned long long p;
    asm("mov.b64 %0, {%1, %2};" : "=l"(p)
        : "r"(__float_as_uint(lo)), "r"(__float_as_uint(hi)));
    return p;
}
__device__ __forceinline__ void unpk2(unsigned long long v,
                                      float& lo, float& hi) {
    unsigned a, b;
    asm("mov.b64 {%0, %1}, %2;" : "=r"(a), "=r"(b) : "l"(v));
    lo = __uint_as_float(a);
    hi = __uint_as_float(b);
}
__device__ __forceinline__ unsigned packh2(float a, float b) {
    __half2 h = __floats2half2_rn(a, b);   // lo = a, hi = b
    return *(unsigned*)&h;
}

// m16n8k16 f16 MMA, f32 accumulate (HMMA path on sm_103a).
__device__ __forceinline__ void mma16816(float& c0, float& c1, float& c2, float& c3,
                                         unsigned a0, unsigned a1, unsigned a2, unsigned a3,
                                         unsigned b0, unsigned b1) {
    asm("mma.sync.aligned.m16n8k16.row.col.f32.f16.f16.f32 "
        "{%0,%1,%2,%3},{%4,%5,%6,%7},{%8,%9},{%0,%1,%2,%3};"
        : "+f"(c0), "+f"(c1), "+f"(c2), "+f"(c3)
        : "r"(a0), "r"(a1), "r"(a2), "r"(a3), "r"(b0), "r"(b1));
}

// ---------------------------------------------------------------------------
// Projection GEMM on the TENSOR pipe (f16 inputs, f32 accumulate).
// BM=64, BN=32, BK=32, 128 threads (4 warps: 2m x 2n, warp tile 32m x 16n).
// Blocks [0,512)=enc@Wa, [512,640)=dec@Ua.
// FIX vs R13: A staging now covers the FULL 64x32 tile (4 float4 per thread,
// thread t owns row t>>1, float4 slots (t&1)*4 .. +3; h2 cols 0..14 in-bounds).
// ---------------------------------------------------------------------------
__global__ __launch_bounds__(128) void proj_kernel(
    const float* __restrict__ enc, const float* __restrict__ dec,
    const float* __restrict__ Wa,  const float* __restrict__ Ua)
{
    __shared__ __half2 sA[64][18];   // [m][k/2] h2 pairs along k (16 used + pad)
    __shared__ __half2 sB[32][18];   // [n][k/2] pairs {W[k][n],W[k+1][n]}

    const int bid = blockIdx.x;
    const float* __restrict__ A;
    const float* __restrict__ W;
    float* __restrict__ P;
    int bm, bn;
    if (bid < 512) {
        A = enc; W = Wa; P = g_ep;
        bm = (bid >> 3) * 64; bn = (bid & 7) * 32;
    } else {
        const int r = bid - 512;
        A = dec; W = Ua; P = g_dp;
        bm = (r >> 3) * 64; bn = (r & 7) * 32;
    }

    const int t    = threadIdx.x;
    const int lane = t & 31;
    const int wz   = t >> 5;        // warp id 0..3
    const int wm   = wz & 1;        // m half (rows wm*32..)
    const int wn   = wz >> 1;       // n half (cols wn*16..)
    const int g    = lane >> 2;     // group 0..7
    const int tg   = lane & 3;      // thread-in-group

    float acc[2][2][4];
#pragma unroll
    for (int i = 0; i < 2; i++)
#pragma unroll
        for (int j = 0; j < 2; j++)
#pragma unroll
            for (int q = 0; q < 4; q++) acc[i][j][q] = 0.f;

    // Staging maps
    const int arow = t >> 1;                 // 0..63 (A row)
    const int ah   = (t & 1) * 4;            // A float4 slot base: 0 or 4
    const int kk   = t >> 3;                 // 0..15 (B k-pair index; k rows 2kk,2kk+1)
    const int nq   = t & 7;                  // 0..7  (B float4 col of 32 n)

    // Prefetch tile 0
    float4 pa[4];
#pragma unroll
    for (int j = 0; j < 4; j++)
        pa[j] = *(const float4*)&A[(bm + arow) * H_ + (ah + j) * 4];
    float4 pb0 = *(const float4*)&W[(2 * kk    ) * H_ + bn + nq * 4];
    float4 pb1 = *(const float4*)&W[(2 * kk + 1) * H_ + bn + nq * 4];

    for (int k0 = 0; k0 < H_; k0 += 32) {
        // ---- store staged regs to smem as f16 ----
#pragma unroll
        for (int j = 0; j < 4; j++) {
            uint2 u = {packh2(pa[j].x, pa[j].y), packh2(pa[j].z, pa[j].w)};
            *(uint2*)&sA[arow][(ah + j) * 2] = u;    // h2 cols 0..14, in-bounds
        }
        {
            const float* f0 = (const float*)&pb0;
            const float* f1 = (const float*)&pb1;
#pragma unroll
            for (int j = 0; j < 4; j++) {
                unsigned h = packh2(f0[j], f1[j]);   // {W[2kk][n], W[2kk+1][n]}
                sB[nq * 4 + j][kk] = *(__half2*)&h;
            }
        }
        __syncthreads();

        // ---- prefetch next tile ----
        if (k0 + 32 < H_) {
#pragma unroll
            for (int j = 0; j < 4; j++)
                pa[j] = *(const float4*)&A[(bm + arow) * H_ + k0 + 32 + (ah + j) * 4];
            pb0 = *(const float4*)&W[(k0 + 32 + 2 * kk    ) * H_ + bn + nq * 4];
            pb1 = *(const float4*)&W[(k0 + 32 + 2 * kk + 1) * H_ + bn + nq * 4];
        }

        // ---- 2 k16-steps x (2 m-sub x 2 n-sub) mma ----
#pragma unroll
        for (int s = 0; s < 2; s++) {
            const int kb = s * 8;            // h2 base of this k16 step
            unsigned a[2][4];
#pragma unroll
            for (int ms = 0; ms < 2; ms++) {
                const int r0 = wm * 32 + ms * 16;
                a[ms][0] = *(unsigned*)&sA[r0 + g    ][kb + tg];      // row g,   k 2tg
                a[ms][1] = *(unsigned*)&sA[r0 + g + 8][kb + tg];      // row g+8, k 2tg
                a[ms][2] = *(unsigned*)&sA[r0 + g    ][kb + tg + 4];  // row g,   k 2tg+8
                a[ms][3] = *(unsigned*)&sA[r0 + g + 8][kb + tg + 4];  // row g+8, k 2tg+8
            }
#pragma unroll
            for (int ns = 0; ns < 2; ns++) {
                const int nb = wn * 16 + ns * 8;
                unsigned b0 = *(unsigned*)&sB[nb + g][kb + tg];       // col g, k 2tg
                unsigned b1 = *(unsigned*)&sB[nb + g][kb + tg + 4];   // col g, k 2tg+8
#pragma unroll
                for (int ms = 0; ms < 2; ms++) {
                    mma16816(acc[ms][ns][0], acc[ms][ns][1],
                             acc[ms][ns][2], acc[ms][ns][3],
                             a[ms][0], a[ms][1], a[ms][2], a[ms][3], b0, b1);
                }
            }
        }
        __syncthreads();
    }

    // ---- epilogue: c0,c1 -> (row g, col 2tg..2tg+1); c2,c3 -> (row g+8, ...) ----
#pragma unroll
    for (int ms = 0; ms < 2; ms++) {
#pragma unroll
        for (int ns = 0; ns < 2; ns++) {
            const int row = bm + wm * 32 + ms * 16 + g;
            const int col = bn + wn * 16 + ns * 8 + 2 * tg;
            float2 lo = {acc[ms][ns][0], acc[ms][ns][1]};
            float2 hi = {acc[ms][ns][2], acc[ms][ns][3]};
            *(float2*)&P[row * H_ + col]       = lo;
            *(float2*)&P[(row + 8) * H_ + col] = hi;
        }
    }
}

// ---------------------------------------------------------------------------
// Score kernel, f16x2 tanh edition (measured-best R9 form, unchanged).
// Grid: (TE/32, TD/8, B) = 2048 blocks, 256 threads.
// ---------------------------------------------------------------------------
__global__ __launch_bounds__(256) void score_kernel(const float* __restrict__ V)
{
    __shared__ unsigned sET2[32][33];            // [h-pair][e] f16x2
    __shared__ unsigned sdp2[8][128];            // dp rows as f16x2
    __shared__ unsigned long long sVp[128];      // V as f32x2 pairs

    const int t    = threadIdx.x;
    const int lane = t & 31;
    const int w    = t >> 5;
    const int b    = blockIdx.z;
    const int d0   = blockIdx.y * 8;
    const int e0   = blockIdx.x * 32;

    {
        const float4* dpsrc = (const float4*)(g_dp + (b * TD_ + d0) * H_);
#pragma unroll
        for (int i = 0; i < 2; i++) {
            int idx = t + i * 256;
            int row = idx >> 6, colq = idx & 63;
            float4 v = dpsrc[row * 64 + colq];
            sdp2[row][colq * 2]     = packh2(v.x, v.y);
            sdp2[row][colq * 2 + 1] = packh2(v.z, v.w);
        }
        if (t < 128) {
            float2 vv = ((const float2*)V)[t];
            sVp[t] = pk2(vv.x, vv.y);
        }
    }

    const float* ep = g_ep + b * TE_ * H_;
    unsigned long long acc = 0ull;

    for (int ht = 0; ht < 4; ++ht) {
        __syncthreads();
#pragma unroll
        for (int i = 0; i < 2; i++) {
            int idx = t + i * 256;
            int e_row = idx >> 4, hq = idx & 15;
            float4 v = *(const float4*)&ep[(e0 + e_row) * H_ + ht * 64 + hq * 4];
            sET2[hq * 2    ][e_row] = packh2(v.x, v.y);
            sET2[hq * 2 + 1][e_row] = packh2(v.z, v.w);
        }
        __syncthreads();

        const unsigned* dprow = &sdp2[w][ht * 32];
        const unsigned long long* vrow = &sVp[ht * 32];
#pragma unroll
        for (int hp = 0; hp < 32; ++hp) {
            unsigned ep2 = sET2[hp][lane];
            unsigned dp2 = dprow[hp];
            __half2 arg = __hadd2(*(__half2*)&ep2, *(__half2*)&dp2);
            unsigned t2 = tanh2_fast(*(unsigned*)&arg);
            __half2 th = *(__half2*)&t2;
            float lo = __low2float(th);
            float hi = __high2float(th);
            ffma2(acc, vrow[hp], pk2(lo, hi));
        }
    }

    float slo, shi;
    unpk2(acc, slo, shi);
    g_score[(b * TD_ + d0 + w) * TE_ + e0 + lane] = slo + shi;
}

// ---------------------------------------------------------------------------
// Softmax (measured-best R9 form). Grid: 128 blocks x 8 warps = 1024 rows.
// ---------------------------------------------------------------------------
__global__ __launch_bounds__(256) void softmax_kernel(float* __restrict__ out)
{
    const int t    = threadIdx.x;
    const int lane = t & 31;
    const int w    = t >> 5;
    const int row  = blockIdx.x * 8 + w;

    float4* srow = (float4*)(g_score + row * TE_);
    float4 v[4];
    float m = -1e30f;
#pragma unroll
    for (int i = 0; i < 4; i++) {
        v[i] = srow[lane + 32 * i];
        m = fmaxf(m, fmaxf(fmaxf(v[i].x, v[i].y), fmaxf(v[i].z, v[i].w)));
    }
#pragma unroll
    for (int o = 16; o > 0; o >>= 1)
        m = fmaxf(m, __shfl_xor_sync(0xffffffffu, m, o));
    float sum = 0.f;
#pragma unroll
    for (int i = 0; i < 4; i++) {
        v[i].x = __expf(v[i].x - m);
        v[i].y = __expf(v[i].y - m);
        v[i].z = __expf(v[i].z - m);
        v[i].w = __expf(v[i].w - m);
        sum += v[i].x + v[i].y + v[i].z + v[i].w;
    }
#pragma unroll
    for (int o = 16; o > 0; o >>= 1)
        sum += __shfl_xor_sync(0xffffffffu, sum, o);
    const float inv = __fdividef(1.f, sum);
    float4* gout = (float4*)(out + (size_t)B_ * TD_ * H_ + row * TE_);
#pragma unroll
    for (int i = 0; i < 4; i++) {
        v[i].x *= inv; v[i].y *= inv; v[i].z *= inv; v[i].w *= inv;
        srow[lane + 32 * i] = v[i];
        gout[lane + 32 * i] = v[i];
    }
}

// ---------------------------------------------------------------------------
// Context partials (measured-best R6/R9 version, unchanged).
// Grid: ((H/64)*ESPLIT, TD/32, B) = (16, 4, 8) = 512 blocks, 256 threads.
// ---------------------------------------------------------------------------
__global__ __launch_bounds__(256) void ctx_part_kernel(
    const float* __restrict__ enc)
{
    __shared__ float sE[128][64];    // 32 KB: enc slab [e][h]
    __shared__ float sWt[32][128];   // 16 KB: weights slab [d][e]

    const int t    = threadIdx.x;
    const int lane = t & 31;
    const int w    = t >> 5;
    const int b    = blockIdx.z;
    const int d0   = blockIdx.y * 32;
    const int hq   = blockIdx.x & 3;
    const int es   = blockIdx.x >> 2;
    const int h0   = hq * 64;
    const int e0   = es * 128;

    const float* enc_b = enc + b * TE_ * H_;
    const float* wbase = g_score + (b * TD_ + d0) * TE_;

#pragma unroll
    for (int i = 0; i < 8; i++) {
        int idx = t + i * 256;
        int row = idx >> 4, col = (idx & 15) * 4;
        *(float4*)&sE[row][col] =
            *(const float4*)&enc_b[(e0 + row) * H_ + h0 + col];
    }
#pragma unroll
    for (int i = 0; i < 4; i++) {
        int idx = t + i * 256;
        int row = idx >> 5, col = (idx & 31) * 4;
        *(float4*)&sWt[row][col] =
            *(const float4*)&wbase[row * TE_ + e0 + col];
    }
    __syncthreads();

    unsigned long long acc[4] = {0ull, 0ull, 0ull, 0ull};

#pragma unroll 2
    for (int e4 = 0; e4 < 32; ++e4) {
        float4 wr0 = *(const float4*)&sWt[w     ][e4 * 4];
        float4 wr1 = *(const float4*)&sWt[w +  8][e4 * 4];
        float4 wr2 = *(const float4*)&sWt[w + 16][e4 * 4];
        float4 wr3 = *(const float4*)&sWt[w + 24][e4 * 4];
        const float* f0 = (const float*)&wr0;
        const float* f1 = (const float*)&wr1;
        const float* f2 = (const float*)&wr2;
        const float* f3 = (const float*)&wr3;
#pragma unroll
        for (int j = 0; j < 4; j++) {
            unsigned long long ev =
                *(const unsigned long long*)&sE[e4 * 4 + j][lane * 2];
            ffma2(acc[0], rep2(f0[j]), ev);
            ffma2(acc[1], rep2(f1[j]), ev);
            ffma2(acc[2], rep2(f2[j]), ev);
            ffma2(acc[3], rep2(f3[j]), ev);
        }
    }

#pragma unroll
    for (int r = 0; r < 4; r++) {
        float lo, hi;
        unpk2(acc[r], lo, hi);
        float2 o = {lo, hi};
        *(float2*)&g_part[es][(b * TD_ + d0 + w + 8 * r) * H_ + h0 + lane * 2] = o;
    }
}

// ---------------------------------------------------------------------------
// Combine: out = (p0+p1)+(p2+p3), fixed order (deterministic).
// Grid 512 x 128 threads (even SM spread, 65536 float4 lanes).
// ---------------------------------------------------------------------------
__global__ __launch_bounds__(128) void combine_kernel(float* __restrict__ out)
{
    const int i = blockIdx.x * 128 + threadIdx.x;
    const float4 p0 = ((const float4*)g_part[0])[i];
    const float4 p1 = ((const float4*)g_part[1])[i];
    const float4 p2 = ((const float4*)g_part[2])[i];
    const float4 p3 = ((const float4*)g_part[3])[i];
    float4 o;
    o.x = (p0.x + p1.x) + (p2.x + p3.x);
    o.y = (p0.y + p1.y) + (p2.y + p3.y);
    o.z = (p0.z + p1.z) + (p2.z + p3.z);
    o.w = (p0.w + p1.w) + (p2.w + p3.w);
    ((float4*)out)[i] = o;
}

// ---------------------------------------------------------------------------
extern "C" void kernel_launch(void* const* d_in, const int* in_sizes, int n_in,
                              void* d_out, int out_size)
{
    const float* enc = (const float*)d_in[0];   // [B,TE,H]
    const float* dec = (const float*)d_in[1];   // [B,TD,H]
    const float* Wa  = (const float*)d_in[2];   // [H,H]
    const float* Ua  = (const float*)d_in[3];   // [H,H]
    const float* Va  = (const float*)d_in[4];   // [H,1]
    float* out = (float*)d_out;                 // context [B,TD,H] then weights [B,TD,TE]

    proj_kernel<<<dim3(640), 128>>>(enc, dec, Wa, Ua);
    score_kernel<<<dim3(TE_ / 32, TD_ / 8, B_), 256>>>(Va);
    softmax_kernel<<<dim3(128), 256>>>(out);
    ctx_part_kernel<<<dim3((H_ / 64) * ESPLIT, TD_ / 32, B_), 256>>>(enc);
    combine_kernel<<<dim3(512), 128>>>(out);
}

// round 15
// speedup vs baseline: 1.3007x; 1.3007x over previous
#include <cuda_runtime.h>
#include <cuda_fp16.h>

#define B_   8
#define TE_  512
#define TD_  128
#define H_   256
#define ESPLIT 4

// Scratch (allocation-free rule: device globals)
__device__ float g_ep[B_ * TE_ * H_];      // enc @ W_a   [B,TE,H]
__device__ float g_dp[B_ * TD_ * H_];      // dec @ U_a   [B,TD,H]
__device__ float g_score[B_ * TD_ * TE_];  // raw scores -> weights (in place)
__device__ float g_part[ESPLIT][B_ * TD_ * H_];  // ctx partial sums (4 MB)

__device__ __forceinline__ unsigned tanh2_fast(unsigned x2) {
    unsigned y2;
    asm("tanh.approx.f16x2 %0, %1;" : "=r"(y2) : "r"(x2));
    return y2;
}
__device__ __forceinline__ void ffma2(unsigned long long& d,
                                      unsigned long long a,
                                      unsigned long long b) {
    asm("fma.rn.f32x2 %0, %1, %2, %0;" : "+l"(d) : "l"(a), "l"(b));
}
__device__ __forceinline__ unsigned long long rep2(float x) {
    unsigned long long p;
    asm("mov.b64 %0, {%1, %1};" : "=l"(p) : "r"(__float_as_uint(x)));
    return p;
}
__device__ __forceinline__ unsigned long long pk2(float lo, float hi) {
    unsigned long long p;
    asm("mov.b64 %0, {%1, %2};" : "=l"(p)
        : "r"(__float_as_uint(lo)), "r"(__float_as_uint(hi)));
    return p;
}
__device__ __forceinline__ void unpk2(unsigned long long v,
                                      float& lo, float& hi) {
    unsigned a, b;
    asm("mov.b64 {%0, %1}, %2;" : "=r"(a), "=r"(b) : "l"(v));
    lo = __uint_as_float(a);
    hi = __uint_as_float(b);
}
__device__ __forceinline__ unsigned packh2(float a, float b) {
    __half2 h = __floats2half2_rn(a, b);   // lo = a, hi = b
    return *(unsigned*)&h;
}

// ---------------------------------------------------------------------------
// Projection GEMM, FFMA2 edition, 256-thread blocks for latency hiding.
// BM=64, BN=32, BK=16. Grid 640: [0,512)=enc@Wa, [512,640)=dec@Ua.
// Thread tile 4m x 2n (acc = 2 f32x2-pairs x 2 cols = 4 FFMA2 per k).
// 8 warps/block (~34 warps/SM) cover the BAR+LDS latency the 128-thread
// R5 version exposed (26us vs 15us FFMA2-rt3 floor).
// ---------------------------------------------------------------------------
__global__ __launch_bounds__(256) void proj_kernel(
    const float* __restrict__ enc, const float* __restrict__ dec,
    const float* __restrict__ Wa,  const float* __restrict__ Ua)
{
    __shared__ float As[16][68];    // A^T tile: As[k][m]  (row stride 272B, 16B-mult)
    __shared__ float Ws[16][36];    // Ws[k][n]            (row stride 144B, 8B-mult)

    const int bid = blockIdx.x;
    const float* __restrict__ A;
    const float* __restrict__ W;
    float* __restrict__ P;
    int bm, bn;
    if (bid < 512) {
        A = enc; W = Wa; P = g_ep;
        bm = (bid >> 3) * 64; bn = (bid & 7) * 32;
    } else {
        const int r = bid - 512;
        A = dec; W = Ua; P = g_dp;
        bm = (r >> 3) * 64; bn = (r & 7) * 32;
    }

    const int t  = threadIdx.x;
    const int tx = t & 15;          // n pair: cols tx*2, tx*2+1
    const int ty = t >> 4;          // m quad: rows ty*4 .. ty*4+3

    unsigned long long acc[2][2];   // acc[i][j]: m pair (4ty+2i,+1), col 2tx+j
    acc[0][0] = 0ull; acc[0][1] = 0ull;
    acc[1][0] = 0ull; acc[1][1] = 0ull;

    // Staging maps
    const int rowA = t >> 2;        // 0..63
    const int kqA  = t & 3;         // float4 k-slot 0..3
    const int kkW  = (t & 127) >> 3;  // 0..15 (threads <128 stage W)
    const int nqW  = t & 7;         // 0..7

    // Prefetch tile 0
    float4 pa = *(const float4*)&A[(bm + rowA) * H_ + kqA * 4];
    float4 pw;
    if (t < 128) pw = *(const float4*)&W[kkW * H_ + bn + nqW * 4];

    for (int k0 = 0; k0 < H_; k0 += 16) {
        // Store staged regs to SMEM (A transposed)
        As[kqA * 4 + 0][rowA] = pa.x;
        As[kqA * 4 + 1][rowA] = pa.y;
        As[kqA * 4 + 2][rowA] = pa.z;
        As[kqA * 4 + 3][rowA] = pa.w;
        if (t < 128)
            *(float4*)&Ws[kkW][nqW * 4] = pw;
        __syncthreads();

        // Prefetch next tile while computing
        if (k0 + 16 < H_) {
            pa = *(const float4*)&A[(bm + rowA) * H_ + k0 + 16 + kqA * 4];
            if (t < 128)
                pw = *(const float4*)&W[(k0 + 16 + kkW) * H_ + bn + nqW * 4];
        }

#pragma unroll
        for (int k = 0; k < 16; k++) {
            ulonglong2 aP = *(const ulonglong2*)&As[k][ty * 4];  // m pairs (0,1),(2,3)
            float2 bv = *(const float2*)&Ws[k][tx * 2];
            unsigned long long b0 = rep2(bv.x);
            unsigned long long b1 = rep2(bv.y);
            ffma2(acc[0][0], aP.x, b0);  ffma2(acc[0][1], aP.x, b1);
            ffma2(acc[1][0], aP.y, b0);  ffma2(acc[1][1], aP.y, b1);
        }
        __syncthreads();
    }

#pragma unroll
    for (int i = 0; i < 2; i++) {
        float l0, h0f, l1, h1f;
        unpk2(acc[i][0], l0, h0f);        // col 2tx:   rows (4ty+2i, +1)
        unpk2(acc[i][1], l1, h1f);        // col 2tx+1
        float2 r0 = {l0, l1};
        float2 r1 = {h0f, h1f};
        *(float2*)&P[(bm + ty * 4 + 2 * i    ) * H_ + bn + tx * 2] = r0;
        *(float2*)&P[(bm + ty * 4 + 2 * i + 1) * H_ + bn + tx * 2] = r1;
    }
}

// ---------------------------------------------------------------------------
// Score kernel, f16x2 tanh edition (measured-best R9 form, unchanged).
// Grid: (TE/32, TD/8, B) = 2048 blocks, 256 threads.
// ---------------------------------------------------------------------------
__global__ __launch_bounds__(256) void score_kernel(const float* __restrict__ V)
{
    __shared__ unsigned sET2[32][33];            // [h-pair][e] f16x2
    __shared__ unsigned sdp2[8][128];            // dp rows as f16x2
    __shared__ unsigned long long sVp[128];      // V as f32x2 pairs

    const int t    = threadIdx.x;
    const int lane = t & 31;
    const int w    = t >> 5;
    const int b    = blockIdx.z;
    const int d0   = blockIdx.y * 8;
    const int e0   = blockIdx.x * 32;

    {
        const float4* dpsrc = (const float4*)(g_dp + (b * TD_ + d0) * H_);
#pragma unroll
        for (int i = 0; i < 2; i++) {
            int idx = t + i * 256;
            int row = idx >> 6, colq = idx & 63;
            float4 v = dpsrc[row * 64 + colq];
            sdp2[row][colq * 2]     = packh2(v.x, v.y);
            sdp2[row][colq * 2 + 1] = packh2(v.z, v.w);
        }
        if (t < 128) {
            float2 vv = ((const float2*)V)[t];
            sVp[t] = pk2(vv.x, vv.y);
        }
    }

    const float* ep = g_ep + b * TE_ * H_;
    unsigned long long acc = 0ull;

    for (int ht = 0; ht < 4; ++ht) {
        __syncthreads();
#pragma unroll
        for (int i = 0; i < 2; i++) {
            int idx = t + i * 256;
            int e_row = idx >> 4, hq = idx & 15;
            float4 v = *(const float4*)&ep[(e0 + e_row) * H_ + ht * 64 + hq * 4];
            sET2[hq * 2    ][e_row] = packh2(v.x, v.y);
            sET2[hq * 2 + 1][e_row] = packh2(v.z, v.w);
        }
        __syncthreads();

        const unsigned* dprow = &sdp2[w][ht * 32];
        const unsigned long long* vrow = &sVp[ht * 32];
#pragma unroll
        for (int hp = 0; hp < 32; ++hp) {
            unsigned ep2 = sET2[hp][lane];
            unsigned dp2 = dprow[hp];
            __half2 arg = __hadd2(*(__half2*)&ep2, *(__half2*)&dp2);
            unsigned t2 = tanh2_fast(*(unsigned*)&arg);
            __half2 th = *(__half2*)&t2;
            float lo = __low2float(th);
            float hi = __high2float(th);
            ffma2(acc, vrow[hp], pk2(lo, hi));
        }
    }

    float slo, shi;
    unpk2(acc, slo, shi);
    g_score[(b * TD_ + d0 + w) * TE_ + e0 + lane] = slo + shi;
}

// ---------------------------------------------------------------------------
// Softmax: normalizes g_score in place and writes the weights output.
// Grid: 256 blocks x 4 warps = 1024 rows (fills 148 SMs).
// ---------------------------------------------------------------------------
__global__ __launch_bounds__(128) void softmax_kernel(float* __restrict__ out)
{
    const int t    = threadIdx.x;
    const int lane = t & 31;
    const int w    = t >> 5;
    const int row  = blockIdx.x * 4 + w;

    float4* srow = (float4*)(g_score + row * TE_);
    float4 v[4];
    float m = -1e30f;
#pragma unroll
    for (int i = 0; i < 4; i++) {
        v[i] = srow[lane + 32 * i];
        m = fmaxf(m, fmaxf(fmaxf(v[i].x, v[i].y), fmaxf(v[i].z, v[i].w)));
    }
#pragma unroll
    for (int o = 16; o > 0; o >>= 1)
        m = fmaxf(m, __shfl_xor_sync(0xffffffffu, m, o));
    float sum = 0.f;
#pragma unroll
    for (int i = 0; i < 4; i++) {
        v[i].x = __expf(v[i].x - m);
        v[i].y = __expf(v[i].y - m);
        v[i].z = __expf(v[i].z - m);
        v[i].w = __expf(v[i].w - m);
        sum += v[i].x + v[i].y + v[i].z + v[i].w;
    }
#pragma unroll
    for (int o = 16; o > 0; o >>= 1)
        sum += __shfl_xor_sync(0xffffffffu, sum, o);
    const float inv = __fdividef(1.f, sum);
    float4* gout = (float4*)(out + (size_t)B_ * TD_ * H_ + row * TE_);
#pragma unroll
    for (int i = 0; i < 4; i++) {
        v[i].x *= inv; v[i].y *= inv; v[i].z *= inv; v[i].w *= inv;
        srow[lane + 32 * i] = v[i];
        gout[lane + 32 * i] = v[i];
    }
}

// ---------------------------------------------------------------------------
// Context partials (measured-best R6/R9 version, unchanged).
// Grid: ((H/64)*ESPLIT, TD/32, B) = (16, 4, 8) = 512 blocks, 256 threads.
// ---------------------------------------------------------------------------
__global__ __launch_bounds__(256) void ctx_part_kernel(
    const float* __restrict__ enc)
{
    __shared__ float sE[128][64];    // 32 KB: enc slab [e][h]
    __shared__ float sWt[32][128];   // 16 KB: weights slab [d][e]

    const int t    = threadIdx.x;
    const int lane = t & 31;
    const int w    = t >> 5;
    const int b    = blockIdx.z;
    const int d0   = blockIdx.y * 32;
    const int hq   = blockIdx.x & 3;
    const int es   = blockIdx.x >> 2;
    const int h0   = hq * 64;
    const int e0   = es * 128;

    const float* enc_b = enc + b * TE_ * H_;
    const float* wbase = g_score + (b * TD_ + d0) * TE_;

#pragma unroll
    for (int i = 0; i < 8; i++) {
        int idx = t + i * 256;
        int row = idx >> 4, col = (idx & 15) * 4;
        *(float4*)&sE[row][col] =
            *(const float4*)&enc_b[(e0 + row) * H_ + h0 + col];
    }
#pragma unroll
    for (int i = 0; i < 4; i++) {
        int idx = t + i * 256;
        int row = idx >> 5, col = (idx & 31) * 4;
        *(float4*)&sWt[row][col] =
            *(const float4*)&wbase[row * TE_ + e0 + col];
    }
    __syncthreads();

    unsigned long long acc[4] = {0ull, 0ull, 0ull, 0ull};

#pragma unroll 2
    for (int e4 = 0; e4 < 32; ++e4) {
        float4 wr0 = *(const float4*)&sWt[w     ][e4 * 4];
        float4 wr1 = *(const float4*)&sWt[w +  8][e4 * 4];
        float4 wr2 = *(const float4*)&sWt[w + 16][e4 * 4];
        float4 wr3 = *(const float4*)&sWt[w + 24][e4 * 4];
        const float* f0 = (const float*)&wr0;
        const float* f1 = (const float*)&wr1;
        const float* f2 = (const float*)&wr2;
        const float* f3 = (const float*)&wr3;
#pragma unroll
        for (int j = 0; j < 4; j++) {
            unsigned long long ev =
                *(const unsigned long long*)&sE[e4 * 4 + j][lane * 2];
            ffma2(acc[0], rep2(f0[j]), ev);
            ffma2(acc[1], rep2(f1[j]), ev);
            ffma2(acc[2], rep2(f2[j]), ev);
            ffma2(acc[3], rep2(f3[j]), ev);
        }
    }

#pragma unroll
    for (int r = 0; r < 4; r++) {
        float lo, hi;
        unpk2(acc[r], lo, hi);
        float2 o = {lo, hi};
        *(float2*)&g_part[es][(b * TD_ + d0 + w + 8 * r) * H_ + h0 + lane * 2] = o;
    }
}

// ---------------------------------------------------------------------------
// Combine: out = (p0+p1)+(p2+p3), fixed order (deterministic).
// Grid 512 x 128 threads (even SM spread, 65536 float4 lanes).
// ---------------------------------------------------------------------------
__global__ __launch_bounds__(128) void combine_kernel(float* __restrict__ out)
{
    const int i = blockIdx.x * 128 + threadIdx.x;
    const float4 p0 = ((const float4*)g_part[0])[i];
    const float4 p1 = ((const float4*)g_part[1])[i];
    const float4 p2 = ((const float4*)g_part[2])[i];
    const float4 p3 = ((const float4*)g_part[3])[i];
    float4 o;
    o.x = (p0.x + p1.x) + (p2.x + p3.x);
    o.y = (p0.y + p1.y) + (p2.y + p3.y);
    o.z = (p0.z + p1.z) + (p2.z + p3.z);
    o.w = (p0.w + p1.w) + (p2.w + p3.w);
    ((float4*)out)[i] = o;
}

// ---------------------------------------------------------------------------
extern "C" void kernel_launch(void* const* d_in, const int* in_sizes, int n_in,
                              void* d_out, int out_size)
{
    const float* enc = (const float*)d_in[0];   // [B,TE,H]
    const float* dec = (const float*)d_in[1];   // [B,TD,H]
    const float* Wa  = (const float*)d_in[2];   // [H,H]
    const float* Ua  = (const float*)d_in[3];   // [H,H]
    const float* Va  = (const float*)d_in[4];   // [H,1]
    float* out = (float*)d_out;                 // context [B,TD,H] then weights [B,TD,TE]

    proj_kernel<<<dim3(640), 256>>>(enc, dec, Wa, Ua);
    score_kernel<<<dim3(TE_ / 32, TD_ / 8, B_), 256>>>(Va);
    softmax_kernel<<<dim3(256), 128>>>(out);
    ctx_part_kernel<<<dim3((H_ / 64) * ESPLIT, TD_ / 32, B_), 256>>>(enc);
    combine_kernel<<<dim3(512), 128>>>(out);
}